// round 9
// baseline (speedup 1.0000x reference)
#include <cuda_runtime.h>
#include <cuda_fp16.h>

#define T_STEPS 256
#define NN      64
#define HH      512
#define DT_C    0.01f
#define NBLK    256
#define NTHR    512
#define NWARP   16
#define CLSZ    4
#define RES_IT  5                                   // resident iters (of 16) per warp
#define DYN_SMEM (NWARP * RES_IT * 2 * 512)         // 81920 B per block

// 64 MiB of fp16 transposed weights: layout [n][j][i]
__device__ __half g_Wh[(size_t)NN * HH * HH];
__device__ __half g_Wx[(size_t)NN * HH * HH];
__device__ unsigned g_state_cnt;        // +1 per block per step (monotonic)

// ---------------------------------------------------------------------------
__device__ __forceinline__ void arrive_rel(unsigned* ctr)
{
    asm volatile("red.release.gpu.add.u32 [%0], 1;" :: "l"(ctr) : "memory");
}
__device__ __forceinline__ unsigned ld_acq(unsigned* ctr)
{
    unsigned v;
    asm volatile("ld.acquire.gpu.u32 %0, [%1];" : "=r"(v) : "l"(ctr) : "memory");
    return v;
}
__device__ __forceinline__ void spin_until(unsigned* ctr, unsigned target)
{
    if (ld_acq(ctr) >= target) return;
    while (ld_acq(ctr) < target) __nanosleep(20);
}

// ---- cluster / DSMEM helpers ----------------------------------------------
__device__ __forceinline__ unsigned smem_u32(const void* p)
{
    unsigned a;
    asm("{ .reg .u64 t; cvta.to.shared.u64 t, %1; cvt.u32.u64 %0, t; }"
        : "=r"(a) : "l"(p));
    return a;
}
__device__ __forceinline__ unsigned mapa_rank(unsigned laddr, int r)
{
    unsigned ra;
    asm("mapa.shared::cluster.u32 %0, %1, %2;" : "=r"(ra) : "r"(laddr), "r"(r));
    return ra;
}
__device__ __forceinline__ void st_cluster_f32(unsigned addr, float v)
{
    asm volatile("st.shared::cluster.f32 [%0], %1;" :: "r"(addr), "f"(v) : "memory");
}
__device__ __forceinline__ void red_cluster_add1(unsigned addr)
{
    asm volatile("red.release.cluster.shared::cluster.add.u32 [%0], 1;"
                 :: "r"(addr) : "memory");
}
__device__ __forceinline__ unsigned lds_vol(const unsigned* p)
{
    unsigned v;
    asm volatile("ld.volatile.shared.u32 %0, [%1];" : "=r"(v) : "r"(smem_u32(p)) : "memory");
    return v;
}
__device__ __forceinline__ void poll_smem(const unsigned* p, unsigned target)
{
    if (lds_vol(p) < target) {
        do { __nanosleep(20); } while (lds_vol(p) < target);
    }
    asm volatile("fence.acq_rel.cluster;" ::: "memory");
}
__device__ __forceinline__ void cluster_sync_arrive_wait()
{
    asm volatile("barrier.cluster.arrive.aligned;" ::: "memory");
    asm volatile("barrier.cluster.wait.aligned;" ::: "memory");
}

// ---------------------------------------------------------------------------
// fp32 [n][i][j]  ->  fp16 [n][j][i]   (transpose + convert, tiled)
// ---------------------------------------------------------------------------
__global__ void convert_transpose_kernel(const float* __restrict__ src, int which)
{
    __shared__ float tile[32][33];
    __half* dst = which ? g_Wx : g_Wh;
    const int nmat = blockIdx.z;
    const float* s = src + (size_t)nmat * HH * HH;
    __half*      d = dst + (size_t)nmat * HH * HH;
    const int x0 = blockIdx.x * 32;
    const int y0 = blockIdx.y * 32;
    #pragma unroll
    for (int k = threadIdx.y; k < 32; k += 8)
        tile[k][threadIdx.x] = s[(size_t)(y0 + k) * HH + x0 + threadIdx.x];
    __syncthreads();
    #pragma unroll
    for (int k = threadIdx.y; k < 32; k += 8)
        d[(size_t)(x0 + k) * HH + y0 + threadIdx.x] = __float2half_rn(tile[threadIdx.x][k]);
}

// ---------------------------------------------------------------------------
__global__ void init_out_kernel(const float* __restrict__ x,
                                const float* __restrict__ init_states,
                                float* __restrict__ states,
                                float* __restrict__ ins)
{
    const int i = blockIdx.x * blockDim.x + threadIdx.x;
    if (i < NN * 2 * HH) states[i] = init_states[i];
    if (i < NN * HH)     ins[i]    = x[i];
    if (i == 0)          g_state_cnt = 0;
}

// ---------------------------------------------------------------------------
__device__ __forceinline__ void fma8(float* acc, uint4 a, float v)
{
    float2 f;
    f = __half22float2(*reinterpret_cast<__half2*>(&a.x)); acc[0] += f.x * v; acc[1] += f.y * v;
    f = __half22float2(*reinterpret_cast<__half2*>(&a.y)); acc[2] += f.x * v; acc[3] += f.y * v;
    f = __half22float2(*reinterpret_cast<__half2*>(&a.z)); acc[4] += f.x * v; acc[5] += f.y * v;
    f = __half22float2(*reinterpret_cast<__half2*>(&a.w)); acc[6] += f.x * v; acc[7] += f.y * v;
}

// ---------------------------------------------------------------------------
// persistent RNN: 256 blocks, cluster of 4 = one neuron, 2 blocks/SM.
// Sibling hy/ins exchange via DSMEM pushes + smem release-counters
// (local LDS polling). Only the all-neuron dependency uses a global counter.
// ---------------------------------------------------------------------------
__global__ void __launch_bounds__(NTHR, 2) __cluster_dims__(CLSZ, 1, 1)
rnn_kernel(
    const float* __restrict__ x,      // [T][N][H]
    const float* __restrict__ C,      // [N][N]
    const float* __restrict__ b,      // [N][H]
    float* __restrict__ states,       // [T+1][N][2][H]
    float* __restrict__ ins)          // [T+1][N][H]
{
    extern __shared__ __align__(16) unsigned char dynsmem[];
    uint4* sres = reinterpret_cast<uint4*>(dynsmem);

    __shared__ __align__(16) float sh_hy[2 * HH];   // parity double buffer
    __shared__ __align__(16) float sh_ins[HH];
    __shared__ float sh_C[NN];
    __shared__ float sh_cm[4 * 128];
    __shared__ float sh_part[NWARP * 128];
    __shared__ unsigned cnt_hy;
    __shared__ unsigned cnt_ins;

    const int bid   = blockIdx.x;
    const int n     = bid >> 2;
    const int ibase = (bid & 3) * 128;
    const int tid   = threadIdx.x;
    const int warp  = tid >> 5;
    const int lane  = tid & 31;
    const int hw    = lane >> 4;
    const int li    = lane & 15;
    const int wbase = warp * 32;

    if (tid == 0) { cnt_hy = 0; cnt_ins = 0; }
    if (tid < NN) sh_C[tid] = C[n * NN + tid];
    const float bias = (tid < 128) ? b[n * HH + ibase + tid] : 0.0f;

    const __half* pWh = g_Wh + (size_t)n * HH * HH + (size_t)(wbase + hw) * HH + ibase + li * 8;
    const __half* pWx = g_Wx + (size_t)n * HH * HH + (size_t)(wbase + hw) * HH + ibase + li * 8;

    // ---- stage resident weights (iters 0..RES_IT-1 of each matrix) ----
    for (int it = 0; it < RES_IT; ++it) {
        sres[((warp * RES_IT + it) * 2 + 0) * 32 + hw * 16 + li] =
            *reinterpret_cast<const uint4*>(pWh + (size_t)it * 2 * HH);
        sres[((warp * RES_IT + it) * 2 + 1) * 32 + hw * 16 + li] =
            *reinterpret_cast<const uint4*>(pWx + (size_t)it * 2 * HH);
    }

    // initial state
    sh_hy[tid] = states[n * 2 * HH + tid];              // parity 0 buffer
    float hz_r = (tid < 128) ? states[(n * 2 + 1) * HH + ibase + tid] : 0.0f;

    const unsigned a_cnt_hy  = smem_u32(&cnt_hy);
    const unsigned a_cnt_ins = smem_u32(&cnt_ins);
    const unsigned a_sh_hy   = smem_u32(sh_hy);
    const unsigned a_sh_ins  = smem_u32(sh_ins);

    __syncthreads();
    cluster_sync_arrive_wait();       // counters initialized cluster-wide

    for (int t = 0; t < T_STEPS; ++t) {
        const float* st  = states + (size_t)t * NN * 2 * HH;
        float*       stn = states + (size_t)(t + 1) * NN * 2 * HH;
        const int par = t & 1;
        const float* hyb = sh_hy + par * HH;

        // ---- wait hy(t) pushes (16 per step: 4 warps x 4 siblings) ---------
        if (t > 0) poll_smem(&cnt_hy, 16u * (unsigned)t);
        const float xv = (tid < 128) ? x[((size_t)t * NN + n) * HH + ibase + tid] : 0.0f;

        float acc[8];
        #pragma unroll
        for (int k = 0; k < 8; ++k) acc[k] = 0.0f;

        // ---- Wh.hy streamed iters (RES_IT..15): hides the global wait ------
        #pragma unroll 4
        for (int it = RES_IT; it < 16; ++it) {
            const float v = hyb[wbase + 2 * it + hw];
            fma8(acc, *reinterpret_cast<const uint4*>(pWh + (size_t)it * 2 * HH), v);
        }

        // ---- global wait: all 256 blocks finished step t-1 ------------------
        if (t > 0) {
            if (tid == 0) spin_until(&g_state_cnt, 256u * (unsigned)t);
            __syncthreads();                                        // bar1
        }

        // ---- distributed C-mix: ins chunk for own 128 j's (4-way m-split) --
        {
            const int jloc = tid & 127;
            const int mg   = tid >> 7;
            float cm = 0.0f;
            if (t > 0) {
                const float* sp = st + (size_t)(2 * mg * 16) * HH + ibase + jloc;
                #pragma unroll 8
                for (int m = 0; m < 16; ++m)
                    cm += sh_C[mg * 16 + m] * sp[(size_t)m * 2 * HH];
            }
            sh_cm[mg * 128 + jloc] = cm;
        }
        __syncthreads();                                            // bar2

        // ---- finalize ins chunk, push to 4 siblings via DSMEM --------------
        if (tid < 128) {
            const float v = (t > 0)
                ? (sh_cm[tid] + sh_cm[128 + tid] + sh_cm[256 + tid] + sh_cm[384 + tid]) * xv
                : 0.0f;
            ins[((size_t)(t + 1) * NN + n) * HH + ibase + tid] = v;   // output (off-chain)
            const unsigned la = a_sh_ins + (unsigned)(ibase + tid) * 4u;
            #pragma unroll
            for (int r = 0; r < CLSZ; ++r)
                st_cluster_f32(mapa_rank(la, r), v);
            __syncwarp();
            if (lane < CLSZ) red_cluster_add1(mapa_rank(a_cnt_ins, lane));
        }

        // ---- Wh.hy resident iters: cover the ins push/poll ------------------
        #pragma unroll
        for (int it = 0; it < RES_IT; ++it) {
            const float v = hyb[wbase + 2 * it + hw];
            fma8(acc, sres[((warp * RES_IT + it) * 2 + 0) * 32 + hw * 16 + li], v);
        }

        // ---- wait full ins(t+1) in local smem --------------------------------
        poll_smem(&cnt_ins, 16u * (unsigned)(t + 1));

        // ---- Wx.ins: resident then streamed ---------------------------------
        #pragma unroll
        for (int it = 0; it < RES_IT; ++it) {
            const float v = sh_ins[wbase + 2 * it + hw];
            fma8(acc, sres[((warp * RES_IT + it) * 2 + 1) * 32 + hw * 16 + li], v);
        }
        #pragma unroll 4
        for (int it = RES_IT; it < 16; ++it) {
            const float v = sh_ins[wbase + 2 * it + hw];
            fma8(acc, *reinterpret_cast<const uint4*>(pWx + (size_t)it * 2 * HH), v);
        }

        // ---- reduce: half-warp pair via shfl, then 16 warps via shared ------
        #pragma unroll
        for (int k = 0; k < 8; ++k)
            acc[k] += __shfl_down_sync(0xffffffffu, acc[k], 16);
        if (hw == 0) {
            #pragma unroll
            for (int k = 0; k < 8; ++k)
                sh_part[warp * 128 + li * 8 + k] = acc[k];
        }
        __syncthreads();                                            // bar3

        // ---- state update; push hy(t+1) to siblings' parity buffer ----------
        if (tid < 128) {
            float s = bias;
            #pragma unroll
            for (int w2 = 0; w2 < NWARP; ++w2) s += sh_part[w2 * 128 + tid];
            const float hy   = hyb[ibase + tid];
            const float hz_n = hz_r + DT_C * (tanhf(s) - hy - hz_r);   // GAMMA=EPS=1
            const float hy_n = hy + DT_C * hz_n;
            hz_r = hz_n;
            stn[(n * 2 + 0) * HH + ibase + tid] = hy_n;
            stn[(n * 2 + 1) * HH + ibase + tid] = hz_n;
            const unsigned la = a_sh_hy + (unsigned)((par ^ 1) * HH + ibase + tid) * 4u;
            #pragma unroll
            for (int r = 0; r < CLSZ; ++r)
                st_cluster_f32(mapa_rank(la, r), hy_n);
            __syncwarp();
            if (lane < CLSZ) red_cluster_add1(mapa_rank(a_cnt_hy, lane));
        }
        __syncthreads();                                            // bar4
        if (tid == 0) arrive_rel(&g_state_cnt);    // hy(t+1) visible gpu-wide
    }

    cluster_sync_arrive_wait();       // no peer may exit while pushes in-flight
}

// ---------------------------------------------------------------------------
extern "C" void kernel_launch(void* const* d_in, const int* in_sizes, int n_in,
                              void* d_out, int out_size)
{
    const float* x   = (const float*)d_in[0];   // (256, 64, 512)
    const float* C   = (const float*)d_in[1];   // (64, 64)
    const float* Wh  = (const float*)d_in[2];   // (64, 512, 512)
    const float* Wx  = (const float*)d_in[3];   // (64, 512, 512)
    const float* b   = (const float*)d_in[4];   // (64, 512)
    const float* s0  = (const float*)d_in[5];   // (64, 2, 512)

    float* out    = (float*)d_out;
    float* states = out;                                          // (257,64,2,512)
    float* ins    = out + (size_t)(T_STEPS + 1) * NN * 2 * HH;    // (257,64,512)

    cudaFuncSetAttribute(rnn_kernel, cudaFuncAttributeMaxDynamicSharedMemorySize, DYN_SMEM);

    dim3 tb(32, 8, 1), tg(16, 16, NN);
    convert_transpose_kernel<<<tg, tb>>>(Wh, 0);
    convert_transpose_kernel<<<tg, tb>>>(Wx, 1);
    init_out_kernel<<<(NN * 2 * HH + 255) / 256, 256>>>(x, s0, states, ins);
    rnn_kernel<<<NBLK, NTHR, DYN_SMEM>>>(x, C, b, states, ins);
}

// round 10
// speedup vs baseline: 1.0368x; 1.0368x over previous
#include <cuda_runtime.h>
#include <cuda_fp16.h>

#define T_STEPS 256
#define NN      64
#define HH      512
#define DT_C    0.01f
#define NBLK    256
#define NTHR    512
#define NWARP   16
#define RES_IT  6                                   // resident iters (of 16) per warp
#define DYN_SMEM (NWARP * RES_IT * 2 * 512)         // 98304 B per block

// 64 MiB of fp16 transposed weights: layout [n][j][i]
__device__ __half g_Wh[(size_t)NN * HH * HH];
__device__ __half g_Wx[(size_t)NN * HH * HH];
__device__ unsigned g_chunk_cnt[4 * 32];   // 4 counters, 128 B apart (use [c*32])
__device__ unsigned g_hy_cnt[NN];          // +1 per sibling per step
__device__ unsigned g_ins_cnt[NN];         // +1 per sibling per step

// ---------------------------------------------------------------------------
__device__ __forceinline__ void arrive_rel(unsigned* ctr)
{
    asm volatile("red.release.gpu.add.u32 [%0], 1;" :: "l"(ctr) : "memory");
}
__device__ __forceinline__ unsigned ld_acq(unsigned* ctr)
{
    unsigned v;
    asm volatile("ld.acquire.gpu.u32 %0, [%1];" : "=r"(v) : "l"(ctr) : "memory");
    return v;
}
__device__ __forceinline__ void spin_until(unsigned* ctr, unsigned target)
{
    if (ld_acq(ctr) >= target) return;
    while (ld_acq(ctr) < target) __nanosleep(20);
}

// ---------------------------------------------------------------------------
// fp32 [n][i][j]  ->  fp16 [n][j][i]   (transpose + convert, tiled)
// ---------------------------------------------------------------------------
__global__ void convert_transpose_kernel(const float* __restrict__ src, int which)
{
    __shared__ float tile[32][33];
    __half* dst = which ? g_Wx : g_Wh;
    const int nmat = blockIdx.z;
    const float* s = src + (size_t)nmat * HH * HH;
    __half*      d = dst + (size_t)nmat * HH * HH;
    const int x0 = blockIdx.x * 32;
    const int y0 = blockIdx.y * 32;
    #pragma unroll
    for (int k = threadIdx.y; k < 32; k += 8)
        tile[k][threadIdx.x] = s[(size_t)(y0 + k) * HH + x0 + threadIdx.x];
    __syncthreads();
    #pragma unroll
    for (int k = threadIdx.y; k < 32; k += 8)
        d[(size_t)(x0 + k) * HH + y0 + threadIdx.x] = __float2half_rn(tile[threadIdx.x][k]);
}

// ---------------------------------------------------------------------------
__global__ void init_out_kernel(const float* __restrict__ x,
                                const float* __restrict__ init_states,
                                float* __restrict__ states,
                                float* __restrict__ ins)
{
    const int i = blockIdx.x * blockDim.x + threadIdx.x;
    if (i < NN * 2 * HH) states[i] = init_states[i];
    if (i < NN * HH)     ins[i]    = x[i];
    if (i < NN)          { g_hy_cnt[i] = 0; g_ins_cnt[i] = 0; }
    if (i < 4 * 32)      g_chunk_cnt[i] = 0;
}

// ---------------------------------------------------------------------------
__device__ __forceinline__ void fma8(float* acc, uint4 a, float v)
{
    float2 f;
    f = __half22float2(*reinterpret_cast<__half2*>(&a.x)); acc[0] += f.x * v; acc[1] += f.y * v;
    f = __half22float2(*reinterpret_cast<__half2*>(&a.y)); acc[2] += f.x * v; acc[3] += f.y * v;
    f = __half22float2(*reinterpret_cast<__half2*>(&a.z)); acc[4] += f.x * v; acc[5] += f.y * v;
    f = __half22float2(*reinterpret_cast<__half2*>(&a.w)); acc[6] += f.x * v; acc[7] += f.y * v;
}

// ---------------------------------------------------------------------------
// persistent RNN: 256 blocks = 4 per neuron (each 128 outputs), 2 blocks/SM,
// 512 threads/block -> 32 warps/SM.  (Structure identical to R8 except the
// global dependency is tracked per-chunk: block (n,c)'s C-mix only reads
// hy chunk c of every neuron, written by the 64 blocks sharing c.)
// ---------------------------------------------------------------------------
__global__ void __launch_bounds__(NTHR, 2) rnn_kernel(
    const float* __restrict__ x,      // [T][N][H]
    const float* __restrict__ C,      // [N][N]
    const float* __restrict__ b,      // [N][H]
    float* __restrict__ states,       // [T+1][N][2][H]
    float* __restrict__ ins)          // [T+1][N][H]
{
    extern __shared__ __align__(16) unsigned char dynsmem[];
    uint4* sres = reinterpret_cast<uint4*>(dynsmem);

    __shared__ float sh_hy[HH];
    __shared__ float sh_ins[HH];
    __shared__ float sh_C[NN];
    __shared__ float sh_cm[4 * 128];
    __shared__ float sh_part[NWARP * 128];

    const int bid   = blockIdx.x;
    const int n     = bid >> 2;
    const int c     = bid & 3;
    const int ibase = c * 128;
    const int tid   = threadIdx.x;
    const int warp  = tid >> 5;
    const int lane  = tid & 31;
    const int hw    = lane >> 4;      // row parity within iter
    const int li    = lane & 15;      // i-chunk (8 halves via uint4)
    const int wbase = warp * 32;      // warp's j-range start (32 rows)

    if (tid < NN) sh_C[tid] = C[n * NN + tid];
    const float bias = (tid < 128) ? b[n * HH + ibase + tid] : 0.0f;

    const __half* pWh = g_Wh + (size_t)n * HH * HH + (size_t)(wbase + hw) * HH + ibase + li * 8;
    const __half* pWx = g_Wx + (size_t)n * HH * HH + (size_t)(wbase + hw) * HH + ibase + li * 8;

    // ---- stage resident weights into shared (once): iters 0..RES_IT-1 ----
    for (int it = 0; it < RES_IT; ++it) {
        sres[((warp * RES_IT + it) * 2 + 0) * 32 + hw * 16 + li] =
            *reinterpret_cast<const uint4*>(pWh + (size_t)it * 2 * HH);
        sres[((warp * RES_IT + it) * 2 + 1) * 32 + hw * 16 + li] =
            *reinterpret_cast<const uint4*>(pWx + (size_t)it * 2 * HH);
    }

    // hz for own 128 outputs lives in a register across all steps
    float hz_r = (tid < 128) ? states[(n * 2 + 1) * HH + ibase + tid] : 0.0f;

    __syncthreads();

    for (int t = 0; t < T_STEPS; ++t) {
        const float* st  = states + (size_t)t * NN * 2 * HH;
        float*       stn = states + (size_t)(t + 1) * NN * 2 * HH;

        // ---- wait siblings' hy(t) chunks (cheap: 4 arrivals, usually done) --
        if (t > 0) {
            if (tid == 0) spin_until(&g_hy_cnt[n], 4u * (unsigned)t);
            __syncthreads();
        }
        sh_hy[tid] = st[n * 2 * HH + tid];
        const float xv = (tid < 128) ? x[((size_t)t * NN + n) * HH + ibase + tid] : 0.0f;
        __syncthreads();

        float acc[8];
        #pragma unroll
        for (int k = 0; k < 8; ++k) acc[k] = 0.0f;

        // ---- Wh.hy streamed iters (RES_IT..15): hides the chunk wait -------
        #pragma unroll 5
        for (int it = RES_IT; it < 16; ++it) {
            const float v = sh_hy[wbase + 2 * it + hw];
            fma8(acc, *reinterpret_cast<const uint4*>(pWh + (size_t)it * 2 * HH), v);
        }

        // ---- chunk wait: the 64 blocks sharing chunk c wrote hy(t) ----------
        if (t > 0) {
            if (tid == 0) spin_until(&g_chunk_cnt[c * 32], 64u * (unsigned)t);
            __syncthreads();
        }

        // ---- distributed C-mix: ins chunk for own 128 j's (4-way m-split) --
        {
            const int jloc = tid & 127;
            const int mg   = tid >> 7;           // 0..3
            float cm = 0.0f;
            if (t > 0) {
                const float* sp = st + (size_t)(2 * mg * 16) * HH + ibase + jloc;
                #pragma unroll 8
                for (int m = 0; m < 16; ++m)
                    cm += sh_C[mg * 16 + m] * sp[(size_t)m * 2 * HH];
            }
            sh_cm[mg * 128 + jloc] = cm;
        }
        __syncthreads();
        if (tid < 128) {
            const float v = (t > 0)
                ? (sh_cm[tid] + sh_cm[128 + tid] + sh_cm[256 + tid] + sh_cm[384 + tid]) * xv
                : 0.0f;
            ins[((size_t)(t + 1) * NN + n) * HH + ibase + tid] = v;
        }
        __syncthreads();
        if (tid == 0) arrive_rel(&g_ins_cnt[n]);

        // ---- Wh.hy resident iters: hides the sibling ins wait --------------
        #pragma unroll
        for (int it = 0; it < RES_IT; ++it) {
            const float v = sh_hy[wbase + 2 * it + hw];
            fma8(acc, sres[((warp * RES_IT + it) * 2 + 0) * 32 + hw * 16 + li], v);
        }

        // ---- gather full ins(t+1) ------------------------------------------
        if (tid == 0) spin_until(&g_ins_cnt[n], 4u * (unsigned)(t + 1));
        __syncthreads();
        sh_ins[tid] = ins[((size_t)(t + 1) * NN + n) * HH + tid];
        __syncthreads();

        // ---- Wx.ins: resident iters then streamed ---------------------------
        #pragma unroll
        for (int it = 0; it < RES_IT; ++it) {
            const float v = sh_ins[wbase + 2 * it + hw];
            fma8(acc, sres[((warp * RES_IT + it) * 2 + 1) * 32 + hw * 16 + li], v);
        }
        #pragma unroll 5
        for (int it = RES_IT; it < 16; ++it) {
            const float v = sh_ins[wbase + 2 * it + hw];
            fma8(acc, *reinterpret_cast<const uint4*>(pWx + (size_t)it * 2 * HH), v);
        }

        // ---- reduce: half-warp pair via shfl, then 16 warps via shared ------
        #pragma unroll
        for (int k = 0; k < 8; ++k)
            acc[k] += __shfl_down_sync(0xffffffffu, acc[k], 16);
        if (hw == 0) {
            #pragma unroll
            for (int k = 0; k < 8; ++k)
                sh_part[warp * 128 + li * 8 + k] = acc[k];
        }
        __syncthreads();

        // ---- state update (hz carried in registers) ------------------------
        if (tid < 128) {
            float s = bias;
            #pragma unroll
            for (int w2 = 0; w2 < NWARP; ++w2) s += sh_part[w2 * 128 + tid];
            const float hy   = sh_hy[ibase + tid];
            const float hz_n = hz_r + DT_C * (tanhf(s) - hy - hz_r);   // GAMMA=EPS=1
            const float hy_n = hy + DT_C * hz_n;
            hz_r = hz_n;
            stn[(n * 2 + 0) * HH + ibase + tid] = hy_n;
            stn[(n * 2 + 1) * HH + ibase + tid] = hz_n;
        }
        __syncthreads();
        if (tid == 0) {
            arrive_rel(&g_hy_cnt[n]);          // siblings may start next Wh.hy
            arrive_rel(&g_chunk_cnt[c * 32]);  // chunk group may start next C-mix
        }
    }
}

// ---------------------------------------------------------------------------
extern "C" void kernel_launch(void* const* d_in, const int* in_sizes, int n_in,
                              void* d_out, int out_size)
{
    const float* x   = (const float*)d_in[0];   // (256, 64, 512)
    const float* C   = (const float*)d_in[1];   // (64, 64)
    const float* Wh  = (const float*)d_in[2];   // (64, 512, 512)
    const float* Wx  = (const float*)d_in[3];   // (64, 512, 512)
    const float* b   = (const float*)d_in[4];   // (64, 512)
    const float* s0  = (const float*)d_in[5];   // (64, 2, 512)

    float* out    = (float*)d_out;
    float* states = out;                                          // (257,64,2,512)
    float* ins    = out + (size_t)(T_STEPS + 1) * NN * 2 * HH;    // (257,64,512)

    cudaFuncSetAttribute(rnn_kernel, cudaFuncAttributeMaxDynamicSharedMemorySize, DYN_SMEM);

    dim3 tb(32, 8, 1), tg(16, 16, NN);
    convert_transpose_kernel<<<tg, tb>>>(Wh, 0);
    convert_transpose_kernel<<<tg, tb>>>(Wx, 1);
    init_out_kernel<<<(NN * 2 * HH + 255) / 256, 256>>>(x, s0, states, ins);
    rnn_kernel<<<NBLK, NTHR, DYN_SMEM>>>(x, C, b, states, ins);
}